// round 4
// baseline (speedup 1.0000x reference)
#include <cuda_runtime.h>
#include <cstdint>

// SelfAttention: out = softmax((xWq)(xWk)^T / 64) @ (xWv)
// N=8192 tokens, d_model=256, d_k=d_v=64, fp32 in/out.
// Strategy: tf32 mma.sync flash attention. Kernel 1 projects Q,K,V into
// __device__ scratch; kernel 2 is a Br=Bc=64 flash-attention with
// register-resident Q fragments and online softmax.

#define NTOK 8192
#define NE   256
#define DH   64
#define BR   64
#define BC   64
#define SSTR 68   // smem row stride (floats): pad 64->68 keeps float4 alignment
                  // and makes fragment-read banks (4*row + col) % 32 distinct.

__device__ float g_Q[NTOK * DH];
__device__ float g_K[NTOK * DH];
__device__ float g_V[NTOK * DH];

// round-to-nearest fp32 -> tf32 (unbiased; truncation would bias dot products)
__device__ __forceinline__ uint32_t f2tf(float f) {
    uint32_t u;
    asm("cvt.rna.tf32.f32 %0, %1;" : "=r"(u) : "f"(f));
    return u;
}

// D += A(16x8) * B(8x8), tf32 inputs, fp32 accumulate
__device__ __forceinline__ void mma_tf32(float* d, const uint32_t* a,
                                         uint32_t b0, uint32_t b1) {
    asm volatile(
        "mma.sync.aligned.m16n8k8.row.col.f32.tf32.tf32.f32 "
        "{%0,%1,%2,%3}, {%4,%5,%6,%7}, {%8,%9}, {%0,%1,%2,%3};"
        : "+f"(d[0]), "+f"(d[1]), "+f"(d[2]), "+f"(d[3])
        : "r"(a[0]), "r"(a[1]), "r"(a[2]), "r"(a[3]), "r"(b0), "r"(b1));
}

// ---------------------------------------------------------------------------
// Kernel 1: Q/K/V projection.  C[8192,64] = x[8192,256] @ W[256,64]
// grid (128, 3): blockIdx.y selects {Wq->g_Q, Wk->g_K, Wv->g_V}
// 128 threads = 4 warps; warp w computes rows 16w..16w+15 of a 64-row tile.
// ---------------------------------------------------------------------------
__global__ __launch_bounds__(128) void proj_kernel(
    const float* __restrict__ x,
    const float* __restrict__ Wq,
    const float* __restrict__ Wk,
    const float* __restrict__ Wv)
{
    __shared__ float sX[BR][SSTR];
    __shared__ float sW[64][SSTR];

    const int tid  = threadIdx.x;
    const int w    = tid >> 5;
    const int lane = tid & 31;
    const int g    = lane >> 2;   // groupID (row within fragment)
    const int c    = lane & 3;    // threadID in group (col within fragment)
    const int rb   = blockIdx.x * BR;

    const float* W;
    float* out;
    if (blockIdx.y == 0)      { W = Wq; out = g_Q; }
    else if (blockIdx.y == 1) { W = Wk; out = g_K; }
    else                      { W = Wv; out = g_V; }

    float acc[8][4];
#pragma unroll
    for (int n = 0; n < 8; n++)
#pragma unroll
        for (int k = 0; k < 4; k++) acc[n][k] = 0.f;

    for (int kc = 0; kc < NE; kc += 64) {
        // cooperative loads: 64x64 tiles, 8 float4 per thread each
#pragma unroll
        for (int i = 0; i < 8; i++) {
            int f = tid + 128 * i;
            int row = f >> 4, c4 = (f & 15) << 2;
            *(float4*)&sX[row][c4] = *(const float4*)&x[(rb + row) * NE + kc + c4];
            *(float4*)&sW[row][c4] = *(const float4*)&W[(kc + row) * DH + c4];
        }
        __syncthreads();

#pragma unroll
        for (int kk = 0; kk < 8; kk++) {
            uint32_t a[4];
            a[0] = f2tf(sX[16 * w + g][8 * kk + c]);
            a[1] = f2tf(sX[16 * w + g + 8][8 * kk + c]);
            a[2] = f2tf(sX[16 * w + g][8 * kk + c + 4]);
            a[3] = f2tf(sX[16 * w + g + 8][8 * kk + c + 4]);
#pragma unroll
            for (int n = 0; n < 8; n++) {
                uint32_t b0 = f2tf(sW[8 * kk + c][8 * n + g]);
                uint32_t b1 = f2tf(sW[8 * kk + c + 4][8 * n + g]);
                mma_tf32(acc[n], a, b0, b1);
            }
        }
        __syncthreads();
    }

    const int r0 = rb + 16 * w + g;
#pragma unroll
    for (int n = 0; n < 8; n++) {
        int col = 8 * n + 2 * c;
        *(float2*)&out[r0 * DH + col]       = make_float2(acc[n][0], acc[n][1]);
        *(float2*)&out[(r0 + 8) * DH + col] = make_float2(acc[n][2], acc[n][3]);
    }
}

// ---------------------------------------------------------------------------
// Kernel 2: flash attention. grid 128, 128 threads (4 warps).
// CTA handles 64 query rows; warp w owns rows 16w..16w+15.
// Loops over 128 KV tiles of 64 keys. Q fragments live in registers (scaled
// by 1/64 up front). P is written (tf32) into the retired sK buffer to
// convert accumulator layout -> A-operand layout for the PV mma.
// ---------------------------------------------------------------------------
__global__ __launch_bounds__(128) void attn_kernel(float* __restrict__ out)
{
    __shared__ float sK[BC][SSTR];
    __shared__ float sV[BC][SSTR];

    const int tid  = threadIdx.x;
    const int w    = tid >> 5;
    const int lane = tid & 31;
    const int g    = lane >> 2;
    const int c    = lane & 3;
    const int qb   = blockIdx.x * BR;

    // ---- stage Q block through sK, build register fragments (scaled 1/64)
#pragma unroll
    for (int i = 0; i < 8; i++) {
        int f = tid + 128 * i;
        int row = f >> 4, c4 = (f & 15) << 2;
        *(float4*)&sK[row][c4] = *(const float4*)&g_Q[(qb + row) * DH + c4];
    }
    __syncthreads();

    uint32_t aq[8][4];
    const float qscale = 1.0f / 64.0f;  // reference divides scores by d_kq=64
#pragma unroll
    for (int kk = 0; kk < 8; kk++) {
        aq[kk][0] = f2tf(sK[16 * w + g][8 * kk + c] * qscale);
        aq[kk][1] = f2tf(sK[16 * w + g + 8][8 * kk + c] * qscale);
        aq[kk][2] = f2tf(sK[16 * w + g][8 * kk + c + 4] * qscale);
        aq[kk][3] = f2tf(sK[16 * w + g + 8][8 * kk + c + 4] * qscale);
    }
    __syncthreads();

    float o[8][4];
#pragma unroll
    for (int n = 0; n < 8; n++)
#pragma unroll
        for (int k = 0; k < 4; k++) o[n][k] = 0.f;
    float m0 = -1e30f, m1 = -1e30f;  // running row maxima (2 rows/lane)
    float l0 = 0.f, l1 = 0.f;        // per-lane partial row sums

    for (int kb = 0; kb < NTOK; kb += BC) {
        // ---- load K,V tiles (L2-resident after first wave)
#pragma unroll
        for (int i = 0; i < 8; i++) {
            int f = tid + 128 * i;
            int row = f >> 4, c4 = (f & 15) << 2;
            *(float4*)&sK[row][c4] = *(const float4*)&g_K[(kb + row) * DH + c4];
            *(float4*)&sV[row][c4] = *(const float4*)&g_V[(kb + row) * DH + c4];
        }
        __syncthreads();

        // ---- S = (Q/64) @ K^T   (S[m][key], key tile = 8 n-frags)
        float s[8][4];
#pragma unroll
        for (int j = 0; j < 8; j++)
#pragma unroll
            for (int k = 0; k < 4; k++) s[j][k] = 0.f;
#pragma unroll
        for (int kk = 0; kk < 8; kk++) {
#pragma unroll
            for (int j = 0; j < 8; j++) {
                // B[k][n] = K[key][d]: key = 8j+g, d = 8kk + c (+4)
                uint32_t b0 = f2tf(sK[8 * j + g][8 * kk + c]);
                uint32_t b1 = f2tf(sK[8 * j + g][8 * kk + c + 4]);
                mma_tf32(s[j], aq[kk], b0, b1);
            }
        }

        // ---- online softmax (rows r0 = 16w+g, r1 = r0+8)
        float mx0 = s[0][0], mx1 = s[0][2];
#pragma unroll
        for (int j = 0; j < 8; j++) {
            mx0 = fmaxf(mx0, fmaxf(s[j][0], s[j][1]));
            mx1 = fmaxf(mx1, fmaxf(s[j][2], s[j][3]));
        }
        mx0 = fmaxf(mx0, __shfl_xor_sync(0xffffffffu, mx0, 1));
        mx0 = fmaxf(mx0, __shfl_xor_sync(0xffffffffu, mx0, 2));
        mx1 = fmaxf(mx1, __shfl_xor_sync(0xffffffffu, mx1, 1));
        mx1 = fmaxf(mx1, __shfl_xor_sync(0xffffffffu, mx1, 2));

        float nm0 = fmaxf(m0, mx0), nm1 = fmaxf(m1, mx1);
        float sc0 = __expf(m0 - nm0), sc1 = __expf(m1 - nm1);  // first iter: exp(-inf)=0
        m0 = nm0; m1 = nm1;
        l0 *= sc0; l1 *= sc1;
#pragma unroll
        for (int n = 0; n < 8; n++) {
            o[n][0] *= sc0; o[n][1] *= sc0;
            o[n][2] *= sc1; o[n][3] *= sc1;
        }
#pragma unroll
        for (int j = 0; j < 8; j++) {
            s[j][0] = __expf(s[j][0] - m0);
            s[j][1] = __expf(s[j][1] - m0);
            s[j][2] = __expf(s[j][2] - m1);
            s[j][3] = __expf(s[j][3] - m1);
            l0 += s[j][0] + s[j][1];
            l1 += s[j][2] + s[j][3];
        }

        __syncthreads();  // every warp done reading sK -> safe to overwrite with P

        // ---- P (tf32) -> sK, warp-local rows (fixes C-layout vs A-layout)
#pragma unroll
        for (int j = 0; j < 8; j++) {
            float2 p01 = make_float2(__uint_as_float(f2tf(s[j][0])),
                                     __uint_as_float(f2tf(s[j][1])));
            float2 p23 = make_float2(__uint_as_float(f2tf(s[j][2])),
                                     __uint_as_float(f2tf(s[j][3])));
            *(float2*)&sK[16 * w + g][8 * j + 2 * c]     = p01;
            *(float2*)&sK[16 * w + g + 8][8 * j + 2 * c] = p23;
        }
        __syncwarp();

        // ---- O += P @ V  (k = keys, n-frags = head dim)
#pragma unroll
        for (int kk = 0; kk < 8; kk++) {
            uint32_t a[4];
            a[0] = __float_as_uint(sK[16 * w + g][8 * kk + c]);
            a[1] = __float_as_uint(sK[16 * w + g + 8][8 * kk + c]);
            a[2] = __float_as_uint(sK[16 * w + g][8 * kk + c + 4]);
            a[3] = __float_as_uint(sK[16 * w + g + 8][8 * kk + c + 4]);
#pragma unroll
            for (int n = 0; n < 8; n++) {
                // B[k][n] = V[key][d]: key = 8kk + c (+4), d = 8n + g
                uint32_t b0 = f2tf(sV[8 * kk + c][8 * n + g]);
                uint32_t b1 = f2tf(sV[8 * kk + c + 4][8 * n + g]);
                mma_tf32(o[n], a, b0, b1);
            }
        }
        __syncthreads();  // done with sV / P before next tile load
    }

    // ---- finalize: full row sums, normalize, store
    l0 += __shfl_xor_sync(0xffffffffu, l0, 1);
    l0 += __shfl_xor_sync(0xffffffffu, l0, 2);
    l1 += __shfl_xor_sync(0xffffffffu, l1, 1);
    l1 += __shfl_xor_sync(0xffffffffu, l1, 2);
    const float i0 = 1.f / l0, i1 = 1.f / l1;

    const int r0 = qb + 16 * w + g;
#pragma unroll
    for (int n = 0; n < 8; n++) {
        int col = 8 * n + 2 * c;
        *(float2*)&out[r0 * DH + col]       = make_float2(o[n][0] * i0, o[n][1] * i0);
        *(float2*)&out[(r0 + 8) * DH + col] = make_float2(o[n][2] * i1, o[n][3] * i1);
    }
}

extern "C" void kernel_launch(void* const* d_in, const int* in_sizes, int n_in,
                              void* d_out, int out_size) {
    const float* x  = (const float*)d_in[0];
    const float* Wq = (const float*)d_in[1];
    const float* Wk = (const float*)d_in[2];
    const float* Wv = (const float*)d_in[3];
    float* out = (float*)d_out;

    proj_kernel<<<dim3(NTOK / BR, 3), 128>>>(x, Wq, Wk, Wv);
    attn_kernel<<<NTOK / BR, 128>>>(out);
}